// round 5
// baseline (speedup 1.0000x reference)
#include <cuda_runtime.h>

typedef unsigned long long ull;

#define Bn 256
#define Tn 512
#define Dn 64
#define Hn 128
#define BTn (Bn*Tn)

// Scratch (allocation-free rule: __device__ globals)
__device__ float g_Gh[(size_t)BTn*Hn];
__device__ float g_Pz[(size_t)BTn*Hn];
__device__ float g_Pr[(size_t)BTn*Hn];
__device__ float g_Ph[(size_t)BTn*Hn];

__device__ __forceinline__ ull pk2(float x, float y){
    ull r; asm("mov.b64 %0,{%1,%2};" : "=l"(r) : "f"(x), "f"(y)); return r;
}
__device__ __forceinline__ ull fma2(ull a, ull b, ull c){
    ull d; asm("fma.rn.f32x2 %0,%1,%2,%3;" : "=l"(d) : "l"(a), "l"(b), "l"(c)); return d;
}
__device__ __forceinline__ float2 up2(ull v){
    float2 f; asm("mov.b64 {%0,%1},%2;" : "=f"(f.x), "=f"(f.y) : "l"(v)); return f;
}
__device__ __forceinline__ float hadd2(ull v){
    float2 f = up2(v); return f.x + f.y;
}

// ---------------------------------------------------------------------------
// Phase 1: recurrence-free precompute (unchanged from prior rounds).
//   gamma_x = exp(-relu(w_gamma_x*dlt + b_gamma_x))
//   x' = m*x + (1-m)*(gamma_x*xl + (1-gamma_x)*mean)
//   Gh = exp(-relu(dlt @ w_gamma_h + b_gamma_h))
//   Pz = x'@w_zx + m@w_zm + b_z ; Pr = x'@w_rx + m@w_rm + b_r ; Ph = x'@w_hx + m@w_hm + b_h
// ---------------------------------------------------------------------------
__global__ void __launch_bounds__(256,2) phase1_kernel(
    const float* __restrict__ values, const float* __restrict__ masks,
    const float* __restrict__ deltas, const float* __restrict__ emean,
    const float* __restrict__ xlocf,  const float* __restrict__ w_gamma_x,
    const float* __restrict__ w_gamma_h, const float* __restrict__ w_rx,
    const float* __restrict__ w_rm,   const float* __restrict__ w_zx,
    const float* __restrict__ w_zm,   const float* __restrict__ w_hx,
    const float* __restrict__ w_hm,   const float* __restrict__ b_gamma_x,
    const float* __restrict__ b_gamma_h, const float* __restrict__ b_r,
    const float* __restrict__ b_z,    const float* __restrict__ b_h)
{
    __shared__ float sx[2048];   // x' tile [32][64]
    __shared__ float smm[2048];  // m  tile
    __shared__ float sdd[2048];  // dlt tile

    const int tid = threadIdx.x;
    const int rowbase = blockIdx.x * 32;

    for (int idx = tid; idx < 2048; idx += 256) {
        int k = idx & 63;
        int g = rowbase * 64 + idx;
        float x  = values[g];
        float m  = masks[g];
        float d  = deltas[g];
        float xl = xlocf[g];
        float gx = __expf(-fmaxf(fmaf(w_gamma_x[k], d, b_gamma_x[k]), 0.f));
        sx[idx]  = m * x + (1.f - m) * (gx * xl + (1.f - gx) * emean[k]);
        smm[idx] = m;
        sdd[idx] = d;
    }
    __syncthreads();

    const int jp = tid & 63;       // column pair: cols {2jp, 2jp+1}
    const int rb = (tid >> 6) * 8; // 8 rows per thread

    ull aG[8], aZ[8], aR[8], aH[8];
    #pragma unroll
    for (int r = 0; r < 8; r++) { aG[r]=0ull; aZ[r]=0ull; aR[r]=0ull; aH[r]=0ull; }

    const ull* Wg  = (const ull*)w_gamma_h;
    const ull* Wzx = (const ull*)w_zx;  const ull* Wzm = (const ull*)w_zm;
    const ull* Wrx = (const ull*)w_rx;  const ull* Wrm = (const ull*)w_rm;
    const ull* Whx = (const ull*)w_hx;  const ull* Whm = (const ull*)w_hm;

    #pragma unroll 2
    for (int k = 0; k < 64; k++) {
        int wo = k * 64 + jp;
        ull wg  = Wg[wo];
        ull wzx = Wzx[wo], wzm = Wzm[wo];
        ull wrx = Wrx[wo], wrm = Wrm[wo];
        ull whx = Whx[wo], whm = Whm[wo];
        #pragma unroll
        for (int r = 0; r < 8; r++) {
            int o = (rb + r) * 64 + k;
            float xv = sx[o], mv = smm[o], dv = sdd[o];
            ull x2 = pk2(xv, xv);
            ull m2 = pk2(mv, mv);
            ull d2 = pk2(dv, dv);
            aG[r] = fma2(d2, wg,  aG[r]);
            aZ[r] = fma2(x2, wzx, aZ[r]);
            aZ[r] = fma2(m2, wzm, aZ[r]);
            aR[r] = fma2(x2, wrx, aR[r]);
            aR[r] = fma2(m2, wrm, aR[r]);
            aH[r] = fma2(x2, whx, aH[r]);
            aH[r] = fma2(m2, whm, aH[r]);
        }
    }

    float2 bgh = ((const float2*)b_gamma_h)[jp];
    float2 bz  = ((const float2*)b_z)[jp];
    float2 br  = ((const float2*)b_r)[jp];
    float2 bh  = ((const float2*)b_h)[jp];
    float2* Gho = (float2*)g_Gh;
    float2* Pzo = (float2*)g_Pz;
    float2* Pro = (float2*)g_Pr;
    float2* Pho = (float2*)g_Ph;

    #pragma unroll
    for (int r = 0; r < 8; r++) {
        int row = rowbase + rb + r;
        int o = row * 64 + jp;
        float2 v = up2(aG[r]);
        float2 w;
        w.x = __expf(-fmaxf(v.x + bgh.x, 0.f));
        w.y = __expf(-fmaxf(v.y + bgh.y, 0.f));
        Gho[o] = w;
        v = up2(aZ[r]); v.x += bz.x; v.y += bz.y; Pzo[o] = v;
        v = up2(aR[r]); v.x += br.x; v.y += br.y; Pro[o] = v;
        v = up2(aH[r]); v.x += bh.x; v.y += bh.y; Pho[o] = v;
    }
}

// ---------------------------------------------------------------------------
// Phase 2: recurrence with REGISTER-RESIDENT weights.
// 128 CTAs x 2 batch rows. 256 threads: thread = (column j = tid&127,
// k-half = tid>>7). Each thread holds half-columns of Wzh/Wrh/Whh as 96
// packed f32x2 registers. Per step:
//   hg = Gh*h  -> shg (k-pair packed, per row)
//   partial az/ar over own k-half (fma2), exchange via spzr, -> z, r
//   srh = r*hg -> partial ah over own k-half, exchange via spah -> ht, h
// No weight smem traffic; FMA floor ~768 cyc/step.
// ---------------------------------------------------------------------------
__global__ void __launch_bounds__(256,1) phase2_kernel(
    const float* __restrict__ w_zh, const float* __restrict__ w_rh,
    const float* __restrict__ w_hh, float* __restrict__ out, int lastoff)
{
    __shared__ ull  shg0[64], shg1[64];   // hg rows 0/1, k-pair packed (128 floats each)
    __shared__ ull  srh0[64], srh1[64];   // r*hg rows 0/1, k-pair packed
    __shared__ float4 spzr[256];          // (az0,az1,ar0,ar1) partials per (half,j)
    __shared__ float2 spah[256];          // (ah0,ah1) partials per (half,j)

    const int tid  = threadIdx.x;
    const int j    = tid & 127;
    const int half = tid >> 7;            // 0: k in [0,64), 1: k in [64,128)
    const int kbase = half * 64;

    // Load weight half-columns into registers, k-pair packed.
    ull wz[32], wr[32], wh[32];
    #pragma unroll
    for (int kp = 0; kp < 32; kp++) {
        int k0 = kbase + 2 * kp;
        wz[kp] = pk2(w_zh[k0 * Hn + j], w_zh[(k0 + 1) * Hn + j]);
        wr[kp] = pk2(w_rh[k0 * Hn + j], w_rh[(k0 + 1) * Hn + j]);
        wh[kp] = pk2(w_hh[k0 * Hn + j], w_hh[(k0 + 1) * Hn + j]);
    }

    const int b0 = blockIdx.x * 2;
    const int stride_b = Tn * Hn;

    const float* pG0 = g_Gh + b0 * stride_b + j;  const float* pG1 = pG0 + stride_b;
    const float* pZ0 = g_Pz + b0 * stride_b + j;  const float* pZ1 = pZ0 + stride_b;
    const float* pR0 = g_Pr + b0 * stride_b + j;  const float* pR1 = pR0 + stride_b;
    const float* pH0 = g_Ph + b0 * stride_b + j;  const float* pH1 = pH0 + stride_b;
    float* o0 = out + b0 * stride_b + j;
    float* o1 = o0 + stride_b;

    float h0 = 0.f, h1 = 0.f;

    float nG0 = pG0[0], nG1 = pG1[0];
    float nZ0 = pZ0[0], nZ1 = pZ1[0];
    float nR0 = pR0[0], nR1 = pR1[0];
    float nH0 = pH0[0], nH1 = pH1[0];

    float* shg0f = (float*)shg0;  float* shg1f = (float*)shg1;
    float* srh0f = (float*)srh0;  float* srh1f = (float*)srh1;
    const ull* hg0p = shg0 + half * 32;   // own k-half, kp-indexed
    const ull* hg1p = shg1 + half * 32;
    const ull* rh0p = srh0 + half * 32;
    const ull* rh1p = srh1 + half * 32;

    for (int t = 0; t < Tn; t++) {
        float G0 = nG0, G1 = nG1, Z0 = nZ0, Z1 = nZ1;
        float R0 = nR0, R1 = nR1, Hp0 = nH0, Hp1 = nH1;
        int on = (t + 1 < Tn) ? (t + 1) * Hn : t * Hn;
        nG0 = pG0[on]; nG1 = pG1[on];
        nZ0 = pZ0[on]; nZ1 = pZ1[on];
        nR0 = pR0[on]; nR1 = pR1[on];
        nH0 = pH0[on]; nH1 = pH1[on];

        float hg0 = G0 * h0, hg1 = G1 * h1;
        if (half == 0) { shg0f[j] = hg0; shg1f[j] = hg1; }
        __syncthreads();                                   // S1

        ull az0 = 0ull, az1 = 0ull, ar0 = 0ull, ar1 = 0ull;
        #pragma unroll
        for (int kp = 0; kp < 32; kp++) {
            ull hp0 = hg0p[kp];
            ull hp1 = hg1p[kp];
            az0 = fma2(hp0, wz[kp], az0);
            az1 = fma2(hp1, wz[kp], az1);
            ar0 = fma2(hp0, wr[kp], ar0);
            ar1 = fma2(hp1, wr[kp], ar1);
        }
        spzr[half * 128 + j] = make_float4(hadd2(az0), hadd2(az1),
                                           hadd2(ar0), hadd2(ar1));
        __syncthreads();                                   // S2

        float4 q = spzr[(1 - half) * 128 + j];
        float sz0 = Z0 + hadd2(az0) + q.x;
        float sz1 = Z1 + hadd2(az1) + q.y;
        float sr0 = R0 + hadd2(ar0) + q.z;
        float sr1 = R1 + hadd2(ar1) + q.w;
        float z0 = 1.f / (1.f + __expf(-sz0));
        float z1 = 1.f / (1.f + __expf(-sz1));
        float r0 = 1.f / (1.f + __expf(-sr0));
        float r1 = 1.f / (1.f + __expf(-sr1));

        if (half == 0) { srh0f[j] = r0 * hg0; srh1f[j] = r1 * hg1; }
        __syncthreads();                                   // S3

        ull ah0 = 0ull, ah1 = 0ull;
        #pragma unroll
        for (int kp = 0; kp < 32; kp++) {
            ah0 = fma2(rh0p[kp], wh[kp], ah0);
            ah1 = fma2(rh1p[kp], wh[kp], ah1);
        }
        spah[half * 128 + j] = make_float2(hadd2(ah0), hadd2(ah1));
        __syncthreads();                                   // S4

        float2 p = spah[(1 - half) * 128 + j];
        float sa0 = Hp0 + hadd2(ah0) + p.x;
        float sa1 = Hp1 + hadd2(ah1) + p.y;
        float e0 = __expf(2.f * sa0), e1 = __expf(2.f * sa1);
        float th0 = 1.f - 2.f / (e0 + 1.f);
        float th1 = 1.f - 2.f / (e1 + 1.f);

        h0 = (1.f - z0) * hg0 + z0 * th0;
        h1 = (1.f - z1) * hg1 + z1 * th1;

        if (half == 0) {
            o0[t * Hn] = h0;
            o1[t * Hn] = h1;
        }
    }
    if (half == 0) {
        out[lastoff + (b0 + 0) * Hn + j] = h0;
        out[lastoff + (b0 + 1) * Hn + j] = h1;
    }
}

extern "C" void kernel_launch(void* const* d_in, const int* in_sizes, int n_in,
                              void* d_out, int out_size)
{
    const float* values = (const float*)d_in[0];
    const float* masks  = (const float*)d_in[1];
    const float* deltas = (const float*)d_in[2];
    const float* emean  = (const float*)d_in[3];
    const float* xlocf  = (const float*)d_in[4];
    const float* w_gamma_x = (const float*)d_in[5];
    const float* w_gamma_h = (const float*)d_in[6];
    const float* w_rx = (const float*)d_in[7];
    const float* w_rh = (const float*)d_in[8];
    const float* w_rm = (const float*)d_in[9];
    const float* w_zx = (const float*)d_in[10];
    const float* w_zh = (const float*)d_in[11];
    const float* w_zm = (const float*)d_in[12];
    const float* w_hx = (const float*)d_in[13];
    const float* w_hh = (const float*)d_in[14];
    const float* w_hm = (const float*)d_in[15];
    const float* b_gamma_x = (const float*)d_in[16];
    const float* b_gamma_h = (const float*)d_in[17];
    const float* b_r = (const float*)d_in[18];
    const float* b_z = (const float*)d_in[19];
    const float* b_h = (const float*)d_in[20];

    phase1_kernel<<<BTn/32, 256>>>(values, masks, deltas, emean, xlocf,
                                   w_gamma_x, w_gamma_h, w_rx, w_rm, w_zx, w_zm,
                                   w_hx, w_hm, b_gamma_x, b_gamma_h, b_r, b_z, b_h);

    int lastoff = out_size - Bn * Hn;   // h_last tail offset, derived not hard-coded
    phase2_kernel<<<Bn/2, 256>>>(w_zh, w_rh, w_hh, (float*)d_out, lastoff);
}